// round 3
// baseline (speedup 1.0000x reference)
#include <cuda_runtime.h>
#include <math.h>

typedef unsigned long long ull;

#define BQ   4
#define CCH  3
#define HH   512
#define WW   512
#define NPL  32
#define TW   64
#define TH   16
#define HALO 15
#define SH   (TH + 2*HALO)      // 46 halo rows
#define SWP  96                 // E stream [0,48), O stream [48,96)
#define TILE_F (CCH*SH*SWP)     // 13248 floats
#define GSH_F  (NPL*33)         // 1056 floats
#define SMEM_FLOATS (TILE_F + GSH_F + 32)
#define SMEM_BYTES  (SMEM_FLOATS * 4)   // 57344 B dynamic smem

__device__ __forceinline__ ull packf2(float lo, float hi) {
    ull r; asm("mov.b64 %0, {%1, %2};" : "=l"(r) : "f"(lo), "f"(hi)); return r;
}
__device__ __forceinline__ void unpackf2(ull v, float &lo, float &hi) {
    asm("mov.b64 {%0, %1}, %2;" : "=f"(lo), "=f"(hi) : "l"(v));
}
__device__ __forceinline__ float lo_of(ull v) {
    float a, b; unpackf2(v, a, b); return a;
}
__device__ __forceinline__ float hi_of(ull v) {
    float a, b; unpackf2(v, a, b); return b;
}
// packed 2-wide f32 FMA: acc += a*b  (ptxas never emits FFMA2 on its own)
__device__ __forceinline__ void fma2(ull &acc, ull a, ull b) {
    asm("fma.rn.f32x2 %0, %1, %2, %0;" : "+l"(acc) : "l"(a), "l"(b));
}

// symmetric fold index, compile-time
#define SYMI(d) ((d) < 16 ? (d) : 30 - (d))

__global__ void __launch_bounds__(256)
defocus_kernel(const float* __restrict__ sharp,
               const float* __restrict__ coc,
               float* __restrict__ out) {
    extern __shared__ float sm[];
    float* tile = sm;                 // [c][r][96]: even cols +0, odd cols +48
    float* gsh  = sm + TILE_F;        // [32][33] zero-padded 31-tap gaussians
    float* msh  = gsh + GSH_F;        // 31 bucket midpoints

    const int tx  = threadIdx.x;      // 0..15
    const int ty  = threadIdx.y;      // 0..15
    const int tid = ty * 16 + tx;
    const int x0  = blockIdx.x * TW;
    const int y0  = blockIdx.y * TH;
    const int b   = blockIdx.z;

    // ---- weight table: warp 0 builds it (overlaps tile loading) ----
    if (tid < NPL) {
        const int i = tid;
        const double step = 50.0 / 31.0;
        float cocf = (float)(i * step);
        if (i < NPL - 1) msh[i] = (cocf + (float)((i + 1) * step)) * 0.5f;
        float row[31];
#pragma unroll
        for (int j = 0; j < 31; j++) row[j] = 0.0f;
        if (cocf < 0.5f) {
            row[15] = 1.0f;
        } else {
            double cd = (double)cocf;
            int k = (int)(2.0 * cd + 1.0);
            if (!(k & 1)) k++;
            if (k > 31) k = 31;
            double sg = cd / 2.355;
            float inv2 = (float)(1.0 / (2.0 * sg * sg));
            int half = k / 2;
            float tmp[31], s = 0.0f;
            for (int j = 0; j < k; j++) {
                float c = (float)(j - half);
                float e = expf(-c * c * inv2);
                tmp[j] = e; s += e;
            }
            float invs = 1.0f / s;
            for (int j = 0; j < k; j++) row[15 - half + j] = tmp[j] * invs;
        }
        for (int j = 0; j < 31; j++) gsh[i * 33 + j] = row[j];
        gsh[i * 33 + 31] = 0.0f; gsh[i * 33 + 32] = 0.0f;
    }

    // ---- tile load, de-interleaved into E/O column streams ----
#pragma unroll
    for (int c = 0; c < CCH; c++) {
        const float* sc = sharp + ((size_t)(b * CCH + c)) * HH * WW;
        float* tc = tile + c * SH * SWP;
        for (int idx = tid; idx < SH * SWP; idx += 256) {
            int r = idx / SWP;
            int t = idx - r * SWP;
            float v = 0.0f;
            if (t < 94) {
                int gx = x0 - HALO + t;
                int gy = y0 - HALO + r;
                if ((unsigned)gx < (unsigned)WW && (unsigned)gy < (unsigned)HH)
                    v = sc[gy * WW + gx];
            }
            tc[r * SWP + (t & 1) * 48 + (t >> 1)] = v;
        }
    }
    __syncthreads();

    // ---- per-thread: 4 consecutive x-pixels A,B,C,D ----
    const int xA = x0 + 4 * tx;
    const int y  = y0 + ty;
    const float4 c4 = *(const float4*)(coc + ((size_t)b * HH + y) * WW + xA);
    int p0 = 0, p1 = 0, p2 = 0, p3 = 0;
#pragma unroll
    for (int i = 0; i < 31; i++) {
        float m = msh[i];
        p0 += c4.x > m; p1 += c4.y > m; p2 += c4.z > m; p3 += c4.w > m;
    }
    const float* gp0 = gsh + p0 * 33;
    const float* gp1 = gsh + p1 * 33;
    const float* gp2 = gsh + p2 * 33;
    const float* gp3 = gsh + p3 * 33;

    // packed symmetric half-kernels: (A,C) and (B,D) stride-2 pairs
    ull wAC[16], wBD[16];
#pragma unroll
    for (int s = 0; s < 16; s++) {
        wAC[s] = packf2(gp0[s], gp2[s]);
        wBD[s] = packf2(gp1[s], gp3[s]);
    }

    ull acc[6] = {0, 0, 0, 0, 0, 0};   // [c]: AC pair, BD pair

    const float* row0 = tile + ty * SWP + 2 * tx;   // (c=0, dy=0) base

#pragma unroll 1
    for (int dy = 0; dy < 31; dy++) {
        const int sdy = (dy < 16) ? dy : 30 - dy;
        const ull gAC = packf2(gp0[sdy], gp2[sdy]);
        const ull gBD = packf2(gp1[sdy], gp3[sdy]);
        const float* rowp_base = row0 + dy * SWP;
#pragma unroll
        for (int c = 0; c < CCH; c++) {
            const float* rowp = rowp_base + c * (SH * SWP);
            const ull* pe = (const ull*)rowp;          // E stream pairs
            const ull* po = (const ull*)(rowp + 48);   // O stream pairs
            const float e16 = rowp[16];                // E pos 16 (scalar)
            const float o16 = rowp[48 + 16];           // O pos 16

            ull rACa = 0, rACb = 0, rBDa = 0, rBDb = 0;  // 4 chains
            ull ce = pe[0], co = po[0];
#pragma unroll
            for (int m = 0; m < 8; m++) {
                ull ne = 0, no = 0; float nel, nol;
                if (m < 7) {
                    ne = pe[m + 1]; no = po[m + 1];
                    nel = lo_of(ne); nol = lo_of(no);
                } else {
                    nel = e16; nol = o16;
                }
                const ull es = packf2(hi_of(ce), nel); // E-pair @ odd pos
                const ull os = packf2(hi_of(co), nol); // O-pair @ odd pos
                // d = 4m .. 4m+3 (d=31 skipped at m=7)
                fma2(rACa, wAC[SYMI(4*m)],     ce);
                fma2(rBDa, wBD[SYMI(4*m)],     co);
                fma2(rACb, wAC[SYMI(4*m + 1)], co);
                fma2(rBDb, wBD[SYMI(4*m + 1)], es);
                fma2(rACa, wAC[SYMI(4*m + 2)], es);
                fma2(rBDa, wBD[SYMI(4*m + 2)], os);
                if (m < 7) {
                    fma2(rACb, wAC[SYMI(4*m + 3)], os);
                    fma2(rBDb, wBD[SYMI(4*m + 3)], ne);
                }
                ce = ne; co = no;
            }
            fma2(acc[2 * c],     gAC, rACa);
            fma2(acc[2 * c],     gAC, rACb);
            fma2(acc[2 * c + 1], gBD, rBDa);
            fma2(acc[2 * c + 1], gBD, rBDb);
        }
    }

    // ---- store: unpack (A,C),(B,D) -> float4 (A,B,C,D) ----
    float* ob = out + (size_t)b * CCH * HH * WW;
#pragma unroll
    for (int c = 0; c < CCH; c++) {
        float a, cc, bb, dd;
        unpackf2(acc[2 * c],     a,  cc);
        unpackf2(acc[2 * c + 1], bb, dd);
        *(float4*)(ob + ((size_t)c * HH + y) * WW + xA) = make_float4(a, bb, cc, dd);
    }
}

// ---------------------------------------------------------------------------
extern "C" void kernel_launch(void* const* d_in, const int* in_sizes, int n_in,
                              void* d_out, int out_size) {
    const float* sharp = (const float*)d_in[0];
    const float* coc   = (const float*)d_in[1];
    if (n_in >= 2 && in_sizes[0] == BQ * HH * WW && in_sizes[1] == BQ * CCH * HH * WW) {
        sharp = (const float*)d_in[1];   // defensive input-order swap
        coc   = (const float*)d_in[0];
    }
    float* out = (float*)d_out;

    cudaFuncSetAttribute(defocus_kernel,
                         cudaFuncAttributeMaxDynamicSharedMemorySize, SMEM_BYTES);
    dim3 grid(WW / TW, HH / TH, BQ);    // (8, 32, 4)
    dim3 block(16, 16);
    defocus_kernel<<<grid, block, SMEM_BYTES>>>(sharp, coc, out);
}

// round 4
// speedup vs baseline: 1.1133x; 1.1133x over previous
#include <cuda_runtime.h>
#include <math.h>

#define BQ   4
#define CCH  3
#define HH   512
#define WW   512
#define NPL  32
#define TW   64            // tile width  (output pixels)
#define TH   8             // tile height (output pixels)
#define HALO 15
#define SW   (TW + 2*HALO) // 94 valid halo columns
#define SWP  96            // padded shared row stride (floats)
#define SH   (TH + 2*HALO) // 38 halo rows

__global__ void __launch_bounds__(256, 2)
defocus_kernel(const float* __restrict__ sharp,
               const float* __restrict__ coc,
               float* __restrict__ out) {
    __shared__ float tile[CCH][SH][SWP];   // 43776 B
    __shared__ float gsh[NPL][33];         // 4224 B (pad 33: conflict-free)
    __shared__ float msh[32];              // 128 B   -> 48128 B total (<48K)

    const int tid = threadIdx.y * 32 + threadIdx.x;
    const int x0 = blockIdx.x * TW;
    const int y0 = blockIdx.y * TH;
    const int b  = blockIdx.z;

    // ---- weight table: warp 0 rebuilds it in-kernel (overlaps tile load) ----
    if (tid < NPL) {
        const int i = tid;
        const double step = 50.0 / 31.0;
        float cocf = (float)(i * step);                 // f32 linspace value
        if (i < NPL - 1) msh[i] = (cocf + (float)((i + 1) * step)) * 0.5f;
        float row[31];
#pragma unroll
        for (int j = 0; j < 31; j++) row[j] = 0.0f;
        if (cocf < 0.5f) {
            row[15] = 1.0f;                             // identity plane
        } else {
            double cd = (double)cocf;
            int k = (int)(2.0 * cd + 1.0);
            if (!(k & 1)) k++;
            if (k > 31) k = 31;
            double sg = cd / 2.355;
            float inv2 = (float)(1.0 / (2.0 * sg * sg));
            int half = k / 2;
            float tmp[31], s = 0.0f;
            for (int j = 0; j < k; j++) {
                float c = (float)(j - half);
                float e = expf(-c * c * inv2);
                tmp[j] = e; s += e;
            }
            float invs = 1.0f / s;
            for (int j = 0; j < k; j++) row[15 - half + j] = tmp[j] * invs;
        }
        for (int j = 0; j < 31; j++) gsh[i][j] = row[j];
        gsh[i][31] = 0.0f; gsh[i][32] = 0.0f;
    }

    // ---- tile + halo load (zero outside image), coalesced ----
    const float* sb = sharp + (size_t)b * CCH * HH * WW;
#pragma unroll
    for (int c = 0; c < CCH; c++) {
        const float* sc = sb + (size_t)c * HH * WW;
        for (int idx = tid; idx < SH * SWP; idx += 256) {
            int r  = idx / SWP;
            int cc = idx - r * SWP;
            int gx = x0 - HALO + cc;
            int gy = y0 - HALO + r;
            float v = 0.0f;
            if (cc < SW && (unsigned)gx < (unsigned)WW && (unsigned)gy < (unsigned)HH)
                v = sc[gy * WW + gx];
            tile[c][r][cc] = v;
        }
    }
    __syncthreads();

    const int tx = threadIdx.x, ty = threadIdx.y;
    const int xA = x0 + 2 * tx;
    const int y  = y0 + ty;

    // Plane indices for the two pixels (exact reference bucketing).
    const float cA = coc[((size_t)b * HH + y) * WW + xA];
    const float cB = coc[((size_t)b * HH + y) * WW + xA + 1];
    int pA = 0, pB = 0;
#pragma unroll
    for (int i = 0; i < 31; i++) {
        pA += (cA > msh[i]);
        pB += (cB > msh[i]);
    }

    // Per-plane symmetric half-kernels into registers (compile-time dx index).
    float wA[16], wB[16];
#pragma unroll
    for (int j = 0; j < 16; j++) { wA[j] = gsh[pA][j]; wB[j] = gsh[pB][j]; }

    float acc[6] = {0.f, 0.f, 0.f, 0.f, 0.f, 0.f};   // [c][A|B]

    for (int dy = 0; dy < 31; dy++) {
        const int sdy = (dy < 16) ? dy : 30 - dy;
        const float gyA = gsh[pA][sdy];              // runtime dy -> shared read
        const float gyB = gsh[pB][sdy];
#pragma unroll
        for (int c = 0; c < CCH; c++) {
            const float* rp = &tile[c][ty + dy][2 * tx];
            float win[32];
#pragma unroll
            for (int j = 0; j < 16; j++) {           // 16 x LDS.64, conflict-free
                float2 t = *(const float2*)(rp + 2 * j);
                win[2 * j]     = t.x;
                win[2 * j + 1] = t.y;
            }
            float rA0 = 0.f, rA1 = 0.f, rB0 = 0.f, rB1 = 0.f;
#pragma unroll
            for (int dx = 0; dx < 31; dx++) {
                const int sj = (dx < 16) ? dx : 30 - dx;  // symmetry fold
                if (dx & 1) { rA1 += wA[sj] * win[dx]; rB1 += wB[sj] * win[dx + 1]; }
                else        { rA0 += wA[sj] * win[dx]; rB0 += wB[sj] * win[dx + 1]; }
            }
            acc[2 * c]     += gyA * (rA0 + rA1);
            acc[2 * c + 1] += gyB * (rB0 + rB1);
        }
    }

    float* ob = out + (size_t)b * CCH * HH * WW;
#pragma unroll
    for (int c = 0; c < CCH; c++) {
        float2 v;
        v.x = acc[2 * c];
        v.y = acc[2 * c + 1];
        *(float2*)(ob + ((size_t)c * HH + y) * WW + xA) = v;
    }
}

// ---------------------------------------------------------------------------
extern "C" void kernel_launch(void* const* d_in, const int* in_sizes, int n_in,
                              void* d_out, int out_size) {
    const float* sharp = (const float*)d_in[0];
    const float* coc   = (const float*)d_in[1];
    if (n_in >= 2 && in_sizes[0] == BQ * HH * WW && in_sizes[1] == BQ * CCH * HH * WW) {
        sharp = (const float*)d_in[1];   // defensive input-order swap
        coc   = (const float*)d_in[0];
    }
    float* out = (float*)d_out;

    dim3 grid(WW / TW, HH / TH, BQ);    // (8, 64, 4)
    dim3 block(32, 8);
    defocus_kernel<<<grid, block>>>(sharp, coc, out);
}

// round 5
// speedup vs baseline: 1.1220x; 1.0078x over previous
#include <cuda_runtime.h>
#include <math.h>

#define BQ   4
#define CCH  3
#define HH   512
#define WW   512
#define NPL  32
#define TW   64            // tile width  (output pixels)
#define TH   8             // tile height (output pixels)
#define HALO 15
#define SW   (TW + 2*HALO) // 94 valid halo columns
#define SWP  96            // padded shared row stride (floats)
#define SH   (TH + 2*HALO) // 38 halo rows

__global__ void __launch_bounds__(256, 2)
defocus_kernel(const float* __restrict__ sharp,
               const float* __restrict__ coc,
               float* __restrict__ out) {
    __shared__ float tile[CCH][SH][SWP];   // 43776 B
    __shared__ float gsh[NPL][33];         // 4224 B (pad 33: conflict-free)
    __shared__ float msh[32];              // 128 B   -> 48128 B total (<48K)

    const int tid = threadIdx.y * 32 + threadIdx.x;
    const int x0 = blockIdx.x * TW;
    const int y0 = blockIdx.y * TH;
    const int b  = blockIdx.z;

    // ---- weight table, phase 1: UNNORMALIZED entries, block-parallel ----
    // entry (i = plane, j = tap 0..30): nonzero iff |j-15| <= half(i).
    // Hides under the tile load (<=4 expf per thread).
    const double step = 50.0 / 31.0;
#pragma unroll
    for (int idx = tid; idx < NPL * 31; idx += 256) {
        const int i = idx / 31;
        const int j = idx - i * 31;
        const float cocf = (float)(i * step);           // f32 linspace value
        float v;
        if (cocf < 0.5f) {
            v = (j == 15) ? 1.0f : 0.0f;                // identity plane
        } else {
            double cd = (double)cocf;
            int k = (int)(2.0 * cd + 1.0);
            if (!(k & 1)) k++;
            if (k > 31) k = 31;
            const int half = k >> 1;
            const int c = j - 15;
            if (c < -half || c > half) {
                v = 0.0f;
            } else {
                double sg = cd / 2.355;
                float inv2 = (float)(1.0 / (2.0 * sg * sg));
                v = expf(-(float)(c * c) * inv2);
            }
        }
        gsh[i][j] = v;
        if (j >= 31 - 2) gsh[i][j + 2] = 0.0f;          // zero pads 31,32
    }
    if (tid < 31) msh[tid] = ((float)(tid * step) + (float)((tid + 1) * step)) * 0.5f;

    // ---- tile + halo load (zero outside image), coalesced ----
    const float* sb = sharp + (size_t)b * CCH * HH * WW;
#pragma unroll
    for (int c = 0; c < CCH; c++) {
        const float* sc = sb + (size_t)c * HH * WW;
        for (int idx = tid; idx < SH * SWP; idx += 256) {
            int r  = idx / SWP;
            int cc = idx - r * SWP;
            int gx = x0 - HALO + cc;
            int gy = y0 - HALO + r;
            float v = 0.0f;
            if (cc < SW && (unsigned)gx < (unsigned)WW && (unsigned)gy < (unsigned)HH)
                v = sc[gy * WW + gx];
            tile[c][r][cc] = v;
        }
    }
    __syncthreads();

    // ---- weight table, phase 2: normalize each plane row in place ----
    if (tid < NPL) {
        float s = 0.0f;
#pragma unroll
        for (int j = 0; j < 31; j++) s += gsh[tid][j];
        const float invs = 1.0f / s;
#pragma unroll
        for (int j = 0; j < 31; j++) gsh[tid][j] *= invs;
    }
    __syncthreads();

    const int tx = threadIdx.x, ty = threadIdx.y;
    const int xA = x0 + 2 * tx;
    const int y  = y0 + ty;

    // Plane indices for the two pixels (exact reference bucketing).
    const float cA = coc[((size_t)b * HH + y) * WW + xA];
    const float cB = coc[((size_t)b * HH + y) * WW + xA + 1];
    int pA = 0, pB = 0;
#pragma unroll
    for (int i = 0; i < 31; i++) {
        pA += (cA > msh[i]);
        pB += (cB > msh[i]);
    }

    // Per-plane symmetric half-kernels into registers (compile-time dx index).
    float wA[16], wB[16];
#pragma unroll
    for (int j = 0; j < 16; j++) { wA[j] = gsh[pA][j]; wB[j] = gsh[pB][j]; }

    float acc[6] = {0.f, 0.f, 0.f, 0.f, 0.f, 0.f};   // [c][A|B]

    for (int dy = 0; dy < 31; dy++) {
        const int sdy = (dy < 16) ? dy : 30 - dy;
        const float gyA = gsh[pA][sdy];              // runtime dy -> shared read
        const float gyB = gsh[pB][sdy];
#pragma unroll
        for (int c = 0; c < CCH; c++) {
            const float* rp = &tile[c][ty + dy][2 * tx];
            float win[32];
#pragma unroll
            for (int j = 0; j < 16; j++) {           // 16 x LDS.64, conflict-free
                float2 t = *(const float2*)(rp + 2 * j);
                win[2 * j]     = t.x;
                win[2 * j + 1] = t.y;
            }
            float rA0 = 0.f, rA1 = 0.f, rB0 = 0.f, rB1 = 0.f;
#pragma unroll
            for (int dx = 0; dx < 31; dx++) {
                const int sj = (dx < 16) ? dx : 30 - dx;  // symmetry fold
                if (dx & 1) { rA1 += wA[sj] * win[dx]; rB1 += wB[sj] * win[dx + 1]; }
                else        { rA0 += wA[sj] * win[dx]; rB0 += wB[sj] * win[dx + 1]; }
            }
            acc[2 * c]     += gyA * (rA0 + rA1);
            acc[2 * c + 1] += gyB * (rB0 + rB1);
        }
    }

    float* ob = out + (size_t)b * CCH * HH * WW;
#pragma unroll
    for (int c = 0; c < CCH; c++) {
        float2 v;
        v.x = acc[2 * c];
        v.y = acc[2 * c + 1];
        *(float2*)(ob + ((size_t)c * HH + y) * WW + xA) = v;
    }
}

// ---------------------------------------------------------------------------
extern "C" void kernel_launch(void* const* d_in, const int* in_sizes, int n_in,
                              void* d_out, int out_size) {
    const float* sharp = (const float*)d_in[0];
    const float* coc   = (const float*)d_in[1];
    if (n_in >= 2 && in_sizes[0] == BQ * HH * WW && in_sizes[1] == BQ * CCH * HH * WW) {
        sharp = (const float*)d_in[1];   // defensive input-order swap
        coc   = (const float*)d_in[0];
    }
    float* out = (float*)d_out;

    dim3 grid(WW / TW, HH / TH, BQ);    // (8, 64, 4)
    dim3 block(32, 8);
    defocus_kernel<<<grid, block>>>(sharp, coc, out);
}

// round 6
// speedup vs baseline: 1.1839x; 1.0552x over previous
#include <cuda_runtime.h>
#include <math.h>

#define BQ   4
#define CCH  3
#define HH   512
#define WW   512
#define NPL  32
#define TW   64            // tile width  (16 threads x 4 px)
#define TH   8             // tile height
#define HALO 15
#define SW   (TW + 2*HALO) // 94 valid halo columns
#define SWP  96            // padded shared row stride (floats)
#define SH   (TH + 2*HALO) // 38 halo rows

#define SYMI(d) ((d) < 16 ? (d) : 30 - (d))

__global__ void __launch_bounds__(128, 3)
defocus_kernel(const float* __restrict__ sharp,
               const float* __restrict__ coc,
               float* __restrict__ out) {
    __shared__ float tile[CCH][SH][SWP];   // 43776 B
    __shared__ float gsh[NPL][33];         // 4224 B (33: bank-conflict-free)
    __shared__ float msh[32];              // 128 B  -> 48128 B total

    const int tid = threadIdx.y * 16 + threadIdx.x;
    const int x0 = blockIdx.x * TW;
    const int y0 = blockIdx.y * TH;
    const int b  = blockIdx.z;

    // ---- weight table, phase 1: unnormalized entries, block-parallel ----
    const double step = 50.0 / 31.0;
    for (int idx = tid; idx < NPL * 31; idx += 128) {
        const int i = idx / 31;
        const int j = idx - i * 31;
        const float cocf = (float)(i * step);
        float v;
        if (cocf < 0.5f) {
            v = (j == 15) ? 1.0f : 0.0f;
        } else {
            double cd = (double)cocf;
            int k = (int)(2.0 * cd + 1.0);
            if (!(k & 1)) k++;
            if (k > 31) k = 31;
            const int half = k >> 1;
            const int c = j - 15;
            if (c < -half || c > half) {
                v = 0.0f;
            } else {
                double sg = cd / 2.355;
                float inv2 = (float)(1.0 / (2.0 * sg * sg));
                v = expf(-(float)(c * c) * inv2);
            }
        }
        gsh[i][j] = v;
    }
    if (tid < 31) msh[tid] = ((float)(tid * step) + (float)((tid + 1) * step)) * 0.5f;

    // ---- tile + halo load ----
    const float* sb = sharp + (size_t)b * CCH * HH * WW;
#pragma unroll
    for (int c = 0; c < CCH; c++) {
        const float* sc = sb + (size_t)c * HH * WW;
        for (int idx = tid; idx < SH * SWP; idx += 128) {
            int r  = idx / SWP;
            int cc = idx - r * SWP;
            int gx = x0 - HALO + cc;
            int gy = y0 - HALO + r;
            float v = 0.0f;
            if (cc < SW && (unsigned)gx < (unsigned)WW && (unsigned)gy < (unsigned)HH)
                v = sc[gy * WW + gx];
            tile[c][r][cc] = v;
        }
    }
    __syncthreads();

    // ---- weight table, phase 2: normalize rows ----
    if (tid < NPL) {
        float s = 0.0f;
#pragma unroll
        for (int j = 0; j < 31; j++) s += gsh[tid][j];
        const float invs = 1.0f / s;
#pragma unroll
        for (int j = 0; j < 31; j++) gsh[tid][j] *= invs;
    }
    __syncthreads();

    const int tx = threadIdx.x, ty = threadIdx.y;
    const int xA = x0 + 4 * tx;
    const int y  = y0 + ty;

    // Plane indices for 4 consecutive pixels (exact reference bucketing).
    const float4 c4 = *(const float4*)(coc + ((size_t)b * HH + y) * WW + xA);
    int p0 = 0, p1 = 0, p2 = 0, p3 = 0;
#pragma unroll
    for (int i = 0; i < 31; i++) {
        float m = msh[i];
        p0 += c4.x > m; p1 += c4.y > m; p2 += c4.z > m; p3 += c4.w > m;
    }

    // Symmetric half-kernels into registers (compile-time tap index).
    float wA[16], wB[16], wC[16], wD[16];
#pragma unroll
    for (int j = 0; j < 16; j++) {
        wA[j] = gsh[p0][j]; wB[j] = gsh[p1][j];
        wC[j] = gsh[p2][j]; wD[j] = gsh[p3][j];
    }

    float acc[12];                       // [c][px]
#pragma unroll
    for (int i = 0; i < 12; i++) acc[i] = 0.0f;

    // ---- main loop: 15 folded row-pairs + center row ----
#pragma unroll 1
    for (int s = 0; s < 15; s++) {
        const float gA = gsh[p0][s], gB = gsh[p1][s];
        const float gC = gsh[p2][s], gD = gsh[p3][s];
#pragma unroll
        for (int c = 0; c < CCH; c++) {
            const float* ra = &tile[c][ty + s][4 * tx];
            const float* rb = &tile[c][ty + 30 - s][4 * tx];
            float f[36];
#pragma unroll
            for (int m = 0; m < 9; m++) {               // 2x LDS.128 + 4 FADD
                float4 qa = *(const float4*)(ra + 4 * m);
                float4 qb = *(const float4*)(rb + 4 * m);
                f[4*m+0] = qa.x + qb.x; f[4*m+1] = qa.y + qb.y;
                f[4*m+2] = qa.z + qb.z; f[4*m+3] = qa.w + qb.w;
            }
            float a0=0.f,a1=0.f,b0=0.f,b1=0.f,c0=0.f,c1=0.f,d0=0.f,d1=0.f;
#pragma unroll
            for (int dx = 0; dx < 31; dx++) {
                const int sj = SYMI(dx);
                if (dx & 1) {
                    a1 += wA[sj]*f[dx];   b1 += wB[sj]*f[dx+1];
                    c1 += wC[sj]*f[dx+2]; d1 += wD[sj]*f[dx+3];
                } else {
                    a0 += wA[sj]*f[dx];   b0 += wB[sj]*f[dx+1];
                    c0 += wC[sj]*f[dx+2]; d0 += wD[sj]*f[dx+3];
                }
            }
            acc[4*c+0] += gA * (a0 + a1);
            acc[4*c+1] += gB * (b0 + b1);
            acc[4*c+2] += gC * (c0 + c1);
            acc[4*c+3] += gD * (d0 + d1);
        }
    }
    {   // center row s = 15 (no fold)
        const float gA = gsh[p0][15], gB = gsh[p1][15];
        const float gC = gsh[p2][15], gD = gsh[p3][15];
#pragma unroll
        for (int c = 0; c < CCH; c++) {
            const float* ra = &tile[c][ty + 15][4 * tx];
            float f[36];
#pragma unroll
            for (int m = 0; m < 9; m++) {
                float4 qa = *(const float4*)(ra + 4 * m);
                f[4*m+0] = qa.x; f[4*m+1] = qa.y;
                f[4*m+2] = qa.z; f[4*m+3] = qa.w;
            }
            float a0=0.f,a1=0.f,b0=0.f,b1=0.f,c0=0.f,c1=0.f,d0=0.f,d1=0.f;
#pragma unroll
            for (int dx = 0; dx < 31; dx++) {
                const int sj = SYMI(dx);
                if (dx & 1) {
                    a1 += wA[sj]*f[dx];   b1 += wB[sj]*f[dx+1];
                    c1 += wC[sj]*f[dx+2]; d1 += wD[sj]*f[dx+3];
                } else {
                    a0 += wA[sj]*f[dx];   b0 += wB[sj]*f[dx+1];
                    c0 += wC[sj]*f[dx+2]; d0 += wD[sj]*f[dx+3];
                }
            }
            acc[4*c+0] += gA * (a0 + a1);
            acc[4*c+1] += gB * (b0 + b1);
            acc[4*c+2] += gC * (c0 + c1);
            acc[4*c+3] += gD * (d0 + d1);
        }
    }

    // ---- store ----
    float* ob = out + (size_t)b * CCH * HH * WW;
#pragma unroll
    for (int c = 0; c < CCH; c++) {
        *(float4*)(ob + ((size_t)c * HH + y) * WW + xA) =
            make_float4(acc[4*c+0], acc[4*c+1], acc[4*c+2], acc[4*c+3]);
    }
}

// ---------------------------------------------------------------------------
extern "C" void kernel_launch(void* const* d_in, const int* in_sizes, int n_in,
                              void* d_out, int out_size) {
    const float* sharp = (const float*)d_in[0];
    const float* coc   = (const float*)d_in[1];
    if (n_in >= 2 && in_sizes[0] == BQ * HH * WW && in_sizes[1] == BQ * CCH * HH * WW) {
        sharp = (const float*)d_in[1];   // defensive input-order swap
        coc   = (const float*)d_in[0];
    }
    float* out = (float*)d_out;

    dim3 grid(WW / TW, HH / TH, BQ);    // (8, 64, 4)
    dim3 block(16, 8);
    defocus_kernel<<<grid, block>>>(sharp, coc, out);
}

// round 7
// speedup vs baseline: 1.2762x; 1.0780x over previous
#include <cuda_runtime.h>
#include <math.h>

#define BQ   4
#define CCH  3
#define HH   512
#define WW   512
#define NPL  32
#define TW   64            // tile width  (16 threads x 4 px)
#define TH   8             // tile height
#define HALO 15
#define SW   (TW + 2*HALO) // 94 valid halo columns
#define SWP  96            // padded shared row stride (floats)
#define SH   (TH + 2*HALO) // 38 halo rows

#define SYMI(d) ((d) < 16 ? (d) : 30 - (d))

__global__ void __launch_bounds__(128, 4)
defocus_kernel(const float* __restrict__ sharp,
               const float* __restrict__ coc,
               float* __restrict__ out) {
    __shared__ float tile[CCH][SH][SWP];   // 43776 B
    __shared__ float gsh[NPL][33];         // 4224 B (33: bank-conflict-free)
    __shared__ float msh[32];              // 128 B  -> 48128 B total

    const int tid = threadIdx.y * 16 + threadIdx.x;
    const int x0 = blockIdx.x * TW;
    const int y0 = blockIdx.y * TH;
    const int b  = blockIdx.z;

    // ---- weight table, phase 1: unnormalized entries, block-parallel ----
    const double step = 50.0 / 31.0;
    for (int idx = tid; idx < NPL * 31; idx += 128) {
        const int i = idx / 31;
        const int j = idx - i * 31;
        const float cocf = (float)(i * step);
        float v;
        if (cocf < 0.5f) {
            v = (j == 15) ? 1.0f : 0.0f;
        } else {
            double cd = (double)cocf;
            int k = (int)(2.0 * cd + 1.0);
            if (!(k & 1)) k++;
            if (k > 31) k = 31;
            const int half = k >> 1;
            const int c = j - 15;
            if (c < -half || c > half) {
                v = 0.0f;
            } else {
                double sg = cd / 2.355;
                float inv2 = (float)(1.0 / (2.0 * sg * sg));
                v = expf(-(float)(c * c) * inv2);
            }
        }
        gsh[i][j] = v;
    }
    if (tid < 31) msh[tid] = ((float)(tid * step) + (float)((tid + 1) * step)) * 0.5f;

    // ---- tile + halo load ----
    const float* sb = sharp + (size_t)b * CCH * HH * WW;
#pragma unroll
    for (int c = 0; c < CCH; c++) {
        const float* sc = sb + (size_t)c * HH * WW;
        for (int idx = tid; idx < SH * SWP; idx += 128) {
            int r  = idx / SWP;
            int cc = idx - r * SWP;
            int gx = x0 - HALO + cc;
            int gy = y0 - HALO + r;
            float v = 0.0f;
            if (cc < SW && (unsigned)gx < (unsigned)WW && (unsigned)gy < (unsigned)HH)
                v = sc[gy * WW + gx];
            tile[c][r][cc] = v;
        }
    }
    __syncthreads();

    // ---- weight table, phase 2: normalize rows ----
    if (tid < NPL) {
        float s = 0.0f;
#pragma unroll
        for (int j = 0; j < 31; j++) s += gsh[tid][j];
        const float invs = 1.0f / s;
#pragma unroll
        for (int j = 0; j < 31; j++) gsh[tid][j] *= invs;
    }
    __syncthreads();

    const int tx = threadIdx.x, ty = threadIdx.y;
    const int xA = x0 + 4 * tx;
    const int y  = y0 + ty;

    // Plane indices for 4 consecutive pixels (exact reference bucketing).
    const float4 c4 = *(const float4*)(coc + ((size_t)b * HH + y) * WW + xA);
    int p0 = 0, p1 = 0, p2 = 0, p3 = 0;
#pragma unroll
    for (int i = 0; i < 31; i++) {
        float m = msh[i];
        p0 += c4.x > m; p1 += c4.y > m; p2 += c4.z > m; p3 += c4.w > m;
    }

    // Symmetric half-kernels into registers (compile-time tap index).
    float wA[16], wB[16], wC[16], wD[16];
#pragma unroll
    for (int j = 0; j < 16; j++) {
        wA[j] = gsh[p0][j]; wB[j] = gsh[p1][j];
        wC[j] = gsh[p2][j]; wD[j] = gsh[p3][j];
    }

    float acc[12];                       // [c][px]
#pragma unroll
    for (int i = 0; i < 12; i++) acc[i] = 0.0f;

    // ---- main loop: 16 folded row-pairs; s=15 self-pairs with halved gy ----
    // (2f)*(0.5g) == f*g exactly in fp, so the degenerate pair is bit-safe.
#pragma unroll 1
    for (int s = 0; s < 16; s++) {
        const float hs = (s == 15) ? 0.5f : 1.0f;
        const float gA = gsh[p0][s] * hs, gB = gsh[p1][s] * hs;
        const float gC = gsh[p2][s] * hs, gD = gsh[p3][s] * hs;
#pragma unroll
        for (int c = 0; c < CCH; c++) {
            const float* ra = &tile[c][ty + s][4 * tx];
            const float* rb = &tile[c][ty + 30 - s][4 * tx];
            float f[36];
#pragma unroll
            for (int m = 0; m < 9; m++) {               // 2x LDS.128 + 4 FADD
                float4 qa = *(const float4*)(ra + 4 * m);
                float4 qb = *(const float4*)(rb + 4 * m);
                f[4*m+0] = qa.x + qb.x; f[4*m+1] = qa.y + qb.y;
                f[4*m+2] = qa.z + qb.z; f[4*m+3] = qa.w + qb.w;
            }
            float a = 0.f, bb = 0.f, cc = 0.f, d = 0.f;  // 4 chains
#pragma unroll
            for (int dx = 0; dx < 31; dx++) {
                const int sj = SYMI(dx);
                a  += wA[sj] * f[dx];
                bb += wB[sj] * f[dx + 1];
                cc += wC[sj] * f[dx + 2];
                d  += wD[sj] * f[dx + 3];
            }
            acc[4*c+0] += gA * a;
            acc[4*c+1] += gB * bb;
            acc[4*c+2] += gC * cc;
            acc[4*c+3] += gD * d;
        }
    }

    // ---- store ----
    float* ob = out + (size_t)b * CCH * HH * WW;
#pragma unroll
    for (int c = 0; c < CCH; c++) {
        *(float4*)(ob + ((size_t)c * HH + y) * WW + xA) =
            make_float4(acc[4*c+0], acc[4*c+1], acc[4*c+2], acc[4*c+3]);
    }
}

// ---------------------------------------------------------------------------
extern "C" void kernel_launch(void* const* d_in, const int* in_sizes, int n_in,
                              void* d_out, int out_size) {
    const float* sharp = (const float*)d_in[0];
    const float* coc   = (const float*)d_in[1];
    if (n_in >= 2 && in_sizes[0] == BQ * HH * WW && in_sizes[1] == BQ * CCH * HH * WW) {
        sharp = (const float*)d_in[1];   // defensive input-order swap
        coc   = (const float*)d_in[0];
    }
    float* out = (float*)d_out;

    dim3 grid(WW / TW, HH / TH, BQ);    // (8, 64, 4)
    dim3 block(16, 8);
    defocus_kernel<<<grid, block>>>(sharp, coc, out);
}